// round 7
// baseline (speedup 1.0000x reference)
#include <cuda_runtime.h>
#include <cuda_bf16.h>
#include <cstdint>

#define MAX_NODES 100000
#define MAX_EDGES 1600000
#define FEAT 64
#define FEAT4 16
#define SCAN_CHUNK 256
#define MAX_SCAN_BLOCKS ((MAX_NODES + SCAN_CHUNK - 1) / SCAN_CHUNK)   // 391

// Scratch (device globals; no allocation allowed)
__device__ int g_count[MAX_NODES];
__device__ int g_off[MAX_NODES + 1];
__device__ int g_cursor[MAX_NODES];
__device__ int g_sorted[MAX_EDGES];
__device__ int g_bsums[MAX_SCAN_BLOCKS];

// ---------------------------------------------------------------------------
// Packed f32x2 helpers (sm_103a dual-issue fp32 FMA; PTX-only path).
// ---------------------------------------------------------------------------
__device__ __forceinline__ uint64_t pack2(float lo, float hi) {
    uint64_t r;
    asm("mov.b64 %0, {%1, %2};" : "=l"(r) : "f"(lo), "f"(hi));
    return r;
}
__device__ __forceinline__ void unpack2(uint64_t v, float& lo, float& hi) {
    asm("mov.b64 {%0, %1}, %2;" : "=f"(lo), "=f"(hi) : "l"(v));
}
__device__ __forceinline__ void ffma2(uint64_t& d, uint64_t a, uint64_t b) {
    asm("fma.rn.f32x2 %0, %1, %2, %0;" : "+l"(d) : "l"(a), "l"(b));
}

// ---------------------------------------------------------------------------
// K0: zero degree counters.
// ---------------------------------------------------------------------------
__global__ void zero_count_kernel(int N) {
    int t = blockIdx.x * blockDim.x + threadIdx.x;
    if (t < N) g_count[t] = 0;
}

// ---------------------------------------------------------------------------
// K1: histogram of dst (degree counts).
// ---------------------------------------------------------------------------
__global__ void hist_kernel(const int* __restrict__ dst, int E) {
    int e = blockIdx.x * blockDim.x + threadIdx.x;
    if (e < E) atomicAdd(&g_count[dst[e]], 1);
}

// ---------------------------------------------------------------------------
// K2a: per-block reduction of counts -> block sums.
// ---------------------------------------------------------------------------
__global__ void scanA_kernel(int N) {
    __shared__ int warp_sums[8];
    int i = blockIdx.x * SCAN_CHUNK + threadIdx.x;
    int v = (i < N) ? g_count[i] : 0;
    for (int o = 16; o > 0; o >>= 1) v += __shfl_down_sync(0xffffffffu, v, o);
    if ((threadIdx.x & 31) == 0) warp_sums[threadIdx.x >> 5] = v;
    __syncthreads();
    if (threadIdx.x < 8) {
        int s = warp_sums[threadIdx.x];
        for (int o = 4; o > 0; o >>= 1) s += __shfl_down_sync(0xffu, s, o);
        if (threadIdx.x == 0) g_bsums[blockIdx.x] = s;
    }
}

// ---------------------------------------------------------------------------
// K2b (fused B+C): each block reduces g_bsums[0..bid) for its base, then does
// the local exclusive scan of its 256 counts -> offsets + cursor copy.
// ---------------------------------------------------------------------------
__global__ void scanC_kernel(int N) {
    __shared__ int s[SCAN_CHUNK];
    __shared__ int sbase;
    int t = threadIdx.x;

    // base = sum of block sums before this block
    int partial = 0;
    for (int b = t; b < (int)blockIdx.x; b += SCAN_CHUNK) partial += g_bsums[b];
    for (int o = 16; o > 0; o >>= 1)
        partial += __shfl_down_sync(0xffffffffu, partial, o);
    if ((t & 31) == 0) s[t >> 5] = partial;
    __syncthreads();
    if (t == 0) {
        int acc = 0;
        for (int w = 0; w < SCAN_CHUNK / 32; w++) acc += s[w];
        sbase = acc;
    }
    __syncthreads();
    int base = sbase;
    __syncthreads();

    // local exclusive scan
    int i = blockIdx.x * SCAN_CHUNK + t;
    int v = (i < N) ? g_count[i] : 0;
    s[t] = v;
    __syncthreads();
    for (int o = 1; o < SCAN_CHUNK; o <<= 1) {
        int x = (t >= o) ? s[t - o] : 0;
        __syncthreads();
        s[t] += x;
        __syncthreads();
    }
    int incl = s[t];
    if (i < N) {
        int off = base + incl - v;
        g_off[i] = off;
        g_cursor[i] = off;
        if (i == N - 1) g_off[N] = base + incl;
    }
}

// ---------------------------------------------------------------------------
// K3: reorder src into dst-sorted order.
// ---------------------------------------------------------------------------
__global__ void reorder_kernel(const int* __restrict__ src,
                               const int* __restrict__ dst, int E) {
    int e = blockIdx.x * blockDim.x + threadIdx.x;
    if (e < E) {
        int d = dst[e];
        int p = atomicAdd(&g_cursor[d], 1);
        g_sorted[p] = src[e];
    }
}

// ---------------------------------------------------------------------------
// K4: fused gather + combine + linear.
// Block = 256 threads handles 64 nodes x 64 outputs.
//
// Smem (k-major / transposed):
//   sXt[128 k][68]: column n holds x[n][k]; k<64 from h, k>=64 from the
//                   gathered neighbor mean (written directly by phase 1).
//   sWt[128 k][68]: column o holds W[o][k].
//
// Phase 1 (staging + gather):
//   - W transpose-staged from gmem.
//   - h part transpose-staged.
//   - neighbor sums: 16 groups of 16 lanes; each group walks 4 nodes' CSR
//     segments; lane owns one float4 feature chunk; writes mean into sXt.
// Phase 2 (GEMM, packed f32x2):
//   thread (ty=tid/16, tx=tid%16): nodes ty*4+i, outs tx*4+j.
//   per k: 1 LDS.128 x (4 nodes), 1 LDS.128 w (2 packed pairs), 8 FFMA2.
// ---------------------------------------------------------------------------
#define TP 68   // row stride (floats); 68*4=272B, 16B-aligned, 4-bank skew
#define FUSED_SMEM_BYTES (2 * 128 * TP * 4)

__global__ void __launch_bounds__(256, 3)
fused_sage_kernel(const float4* __restrict__ h4,
                  const float* __restrict__ W,
                  const float* __restrict__ b,
                  float* __restrict__ out,
                  int N) {
    extern __shared__ float smem[];
    float* sXt = smem;                // [128][TP]
    float* sWt = smem + 128 * TP;     // [128][TP]

    const int tid = threadIdx.x;
    const int nb = blockIdx.x * 64;

    // --- Stage W transposed: 64 o x 32 quads ---
    for (int q = tid; q < 2048; q += 256) {
        int o  = q >> 5;
        int kq = q & 31;
        float4 v = *(const float4*)(W + o * 128 + kq * 4);
        int k = kq * 4;
        sWt[(k + 0) * TP + o] = v.x;
        sWt[(k + 1) * TP + o] = v.y;
        sWt[(k + 2) * TP + o] = v.z;
        sWt[(k + 3) * TP + o] = v.w;
    }

    // --- Stage h part transposed (k < 64): 64 n x 16 quads ---
    for (int q = tid; q < 1024; q += 256) {
        int n = q >> 4;
        int c = q & 15;
        int gn = nb + n;
        float4 v = make_float4(0.f, 0.f, 0.f, 0.f);
        if (gn < N) v = __ldg(h4 + (size_t)gn * FEAT4 + c);
        int k = c * 4;
        sXt[(k + 0) * TP + n] = v.x;
        sXt[(k + 1) * TP + n] = v.y;
        sXt[(k + 2) * TP + n] = v.z;
        sXt[(k + 3) * TP + n] = v.w;
    }

    // --- Gather neighbor means (k >= 64): 16 groups x 16 lanes ---
    {
        int grp  = tid >> 4;
        int lane = tid & 15;
#pragma unroll
        for (int nn = 0; nn < 4; nn++) {
            int n = grp + nn * 16;       // 0..63
            int gn = nb + n;
            float4 acc = make_float4(0.f, 0.f, 0.f, 0.f);
            float inv = 0.f;
            if (gn < N) {
                int beg = g_off[gn];
                int end = g_off[gn + 1];
                int j = beg;
                for (; j + 1 < end; j += 2) {
                    int s0 = g_sorted[j];
                    int s1 = g_sorted[j + 1];
                    float4 v0 = __ldg(h4 + (size_t)s0 * FEAT4 + lane);
                    float4 v1 = __ldg(h4 + (size_t)s1 * FEAT4 + lane);
                    acc.x += v0.x; acc.y += v0.y; acc.z += v0.z; acc.w += v0.w;
                    acc.x += v1.x; acc.y += v1.y; acc.z += v1.z; acc.w += v1.w;
                }
                if (j < end) {
                    int s0 = g_sorted[j];
                    float4 v0 = __ldg(h4 + (size_t)s0 * FEAT4 + lane);
                    acc.x += v0.x; acc.y += v0.y; acc.z += v0.z; acc.w += v0.w;
                }
                inv = 1.0f / fmaxf((float)g_count[gn], 1.0f);
            }
            int k = 64 + lane * 4;
            sXt[(k + 0) * TP + n] = acc.x * inv;
            sXt[(k + 1) * TP + n] = acc.y * inv;
            sXt[(k + 2) * TP + n] = acc.z * inv;
            sXt[(k + 3) * TP + n] = acc.w * inv;
        }
    }
    __syncthreads();

    // --- Phase 2: GEMM with packed f32x2 FMA ---
    const int tx = tid & 15;
    const int ty = tid >> 4;

    uint64_t acc2[4][2];
    {
        uint64_t b01 = pack2(b[tx * 4 + 0], b[tx * 4 + 1]);
        uint64_t b23 = pack2(b[tx * 4 + 2], b[tx * 4 + 3]);
#pragma unroll
        for (int i = 0; i < 4; i++) { acc2[i][0] = b01; acc2[i][1] = b23; }
    }

#pragma unroll 8
    for (int k = 0; k < 128; k++) {
        float4 xv = *(const float4*)(sXt + k * TP + ty * 4);
        const uint64_t* wr = (const uint64_t*)(sWt + k * TP + tx * 4);
        uint64_t w01 = wr[0];
        uint64_t w23 = wr[1];
        uint64_t x0 = pack2(xv.x, xv.x);
        uint64_t x1 = pack2(xv.y, xv.y);
        uint64_t x2 = pack2(xv.z, xv.z);
        uint64_t x3 = pack2(xv.w, xv.w);
        ffma2(acc2[0][0], x0, w01); ffma2(acc2[0][1], x0, w23);
        ffma2(acc2[1][0], x1, w01); ffma2(acc2[1][1], x1, w23);
        ffma2(acc2[2][0], x2, w01); ffma2(acc2[2][1], x2, w23);
        ffma2(acc2[3][0], x3, w01); ffma2(acc2[3][1], x3, w23);
    }

#pragma unroll
    for (int i = 0; i < 4; i++) {
        int gn = nb + ty * 4 + i;
        if (gn < N) {
            float4 r;
            unpack2(acc2[i][0], r.x, r.y);
            unpack2(acc2[i][1], r.z, r.w);
            *(float4*)(out + (size_t)gn * 64 + tx * 4) = r;
        }
    }
}

// ---------------------------------------------------------------------------
// Launch
// ---------------------------------------------------------------------------
extern "C" void kernel_launch(void* const* d_in, const int* in_sizes, int n_in,
                              void* d_out, int out_size) {
    const float* h   = (const float*)d_in[0];
    const int*   src = (const int*)d_in[1];   // int32 indices
    const int*   dst = (const int*)d_in[2];
    const float* W   = (const float*)d_in[3];
    const float* b   = (const float*)d_in[4];
    float*       out = (float*)d_out;

    const int N = in_sizes[0] / FEAT;   // 100000
    const int E = in_sizes[1];          // 1600000
    const int NB = (N + SCAN_CHUNK - 1) / SCAN_CHUNK;   // 391

    zero_count_kernel<<<(N + 255) / 256, 256>>>(N);
    hist_kernel<<<(E + 255) / 256, 256>>>(dst, E);
    scanA_kernel<<<NB, SCAN_CHUNK>>>(N);
    scanC_kernel<<<NB, SCAN_CHUNK>>>(N);
    reorder_kernel<<<(E + 255) / 256, 256>>>(src, dst, E);

    cudaFuncSetAttribute(fused_sage_kernel,
                         cudaFuncAttributeMaxDynamicSharedMemorySize,
                         FUSED_SMEM_BYTES);
    fused_sage_kernel<<<(N + 63) / 64, 256, FUSED_SMEM_BYTES>>>(
        (const float4*)h, W, b, out, N);
}